// round 11
// baseline (speedup 1.0000x reference)
#include <cuda_runtime.h>
#include <cuda_bf16.h>
#include <math.h>
#include <cstdint>

#define Bb 2
#define Nn 1024
#define Cc 768
#define Hh 12
#define Dd 64
#define ATT_SCALE 0.125f   // D^-0.5
#define SKIP_LOG  -30.0f   // tiles with max log-mask below this contribute < 1e-12 relative

// ---------------- scratch (static device memory; no allocations) ----------------
__device__ float g_qkv[Bb * Nn * 3 * Cc];            // fp32 qkv from GEMM
__device__ __nv_bfloat16 g_hi[Bb * Nn * 3 * Cc];     // qkv planes (q/k normalized, v raw)
__device__ __nv_bfloat16 g_lo[Bb * Nn * 3 * Cc];
__device__ __nv_bfloat16 g_xhi[Bb * Nn * Cc],  g_xlo[Bb * Nn * Cc];     // x planes
__device__ __nv_bfloat16 g_w1hi[3 * Cc * Cc],  g_w1lo[3 * Cc * Cc];     // Wqkv planes
__device__ __nv_bfloat16 g_w2hi[Cc * Cc],      g_w2lo[Cc * Cc];         // Wproj planes
__device__ __nv_bfloat16 g_aohi[Bb * Nn * Cc], g_aolo[Bb * Nn * Cc];    // attn out planes
__device__ float g_z  [Bb * Nn * Hh];                // gate logits
__device__ float g_c  [Bb * Hh * (Nn + 1)];          // prefix sums of log a

__device__ __forceinline__ uint32_t smem_u32(const void* p) {
  uint32_t a;
  asm("{ .reg .u64 t; cvta.to.shared.u64 t, %1; cvt.u32.u64 %0, t; }" : "=r"(a) : "l"(p));
  return a;
}

#define LDSM4(R0, R1, R2, R3, addr) \
  asm volatile("ldmatrix.sync.aligned.m8n8.x4.shared.b16 {%0,%1,%2,%3}, [%4];" \
               : "=r"(R0), "=r"(R1), "=r"(R2), "=r"(R3) : "r"(addr))

#define LDSM4T(R0, R1, R2, R3, addr) \
  asm volatile("ldmatrix.sync.aligned.m8n8.x4.trans.shared.b16 {%0,%1,%2,%3}, [%4];" \
               : "=r"(R0), "=r"(R1), "=r"(R2), "=r"(R3) : "r"(addr))

#define MMA16816(C, A0, A1, A2, A3, B0, B1) \
  asm volatile("mma.sync.aligned.m16n8k16.row.col.f32.bf16.bf16.f32 " \
               "{%0,%1,%2,%3}, {%4,%5,%6,%7}, {%8,%9}, {%0,%1,%2,%3};" \
               : "+f"((C)[0]), "+f"((C)[1]), "+f"((C)[2]), "+f"((C)[3]) \
               : "r"(A0), "r"(A1), "r"(A2), "r"(A3), "r"(B0), "r"(B1))

// ---------------- generic fp32 -> bf16 hi/lo plane split (vectorized x4) ----------------
__global__ __launch_bounds__(256) void split_planes(
    const float* __restrict__ src, __nv_bfloat16* __restrict__ hi,
    __nv_bfloat16* __restrict__ lo, int n)
{
  const int i = (blockIdx.x * 256 + threadIdx.x) * 4;
  if (i >= n) return;
  float4 v = *(const float4*)(src + i);
  __nv_bfloat162 h0 = __floats2bfloat162_rn(v.x, v.y);
  float2 f0 = __bfloat1622float2(h0);
  __nv_bfloat162 l0 = __floats2bfloat162_rn(v.x - f0.x, v.y - f0.y);
  __nv_bfloat162 h1 = __floats2bfloat162_rn(v.z, v.w);
  float2 f1 = __bfloat1622float2(h1);
  __nv_bfloat162 l1 = __floats2bfloat162_rn(v.z - f1.x, v.w - f1.y);
  *(uint2*)(hi + i) = make_uint2(*(uint32_t*)&h0, *(uint32_t*)&h1);
  *(uint2*)(lo + i) = make_uint2(*(uint32_t*)&l0, *(uint32_t*)&l1);
}

// ===== tensor-core GEMM (bf16 3-pass split, plane inputs): C = A @ B^T (+bias) =====
#define GPITCH 80
#define GMAT   (128 * GPITCH)
#define GSTAGE (2 * GMAT)
#define GSMEM  (2 * GSTAGE)

__global__ __launch_bounds__(256, 2) void gemm_mma(
    const __nv_bfloat16* __restrict__ Ahi, const __nv_bfloat16* __restrict__ Alo,
    const __nv_bfloat16* __restrict__ Bhi, const __nv_bfloat16* __restrict__ Blo,
    const float* __restrict__ bias, float* __restrict__ Cout,
    int M, int N, int K)
{
  extern __shared__ char smc[];
  const uint32_t sb = smem_u32(smc);
  const int tid = threadIdx.x, wid = tid >> 5, lane = tid & 31;
  const int m0 = blockIdx.y * 128, n0 = blockIdx.x * 128;
  const int wm = (wid & 1) * 64, wn = (wid >> 1) * 32;

  const int lrow = tid >> 1;
  const int lcol = (tid & 1) * 8;
  const size_t arow = (size_t)(m0 + lrow) * K + lcol;
  const size_t brow = (size_t)(n0 + lrow) * K + lcol;
  const uint32_t stOff = (uint32_t)(lrow * GPITCH + (tid & 1) * 16);   // hi; lo at +32

  const uint32_t aoff = (uint32_t)((wm + (lane & 15)) * GPITCH + ((lane >> 4) * 16));
  const uint32_t boff = (uint32_t)((wn + ((lane >> 4) << 3) + (lane & 7)) * GPITCH
                                   + (((lane >> 3) & 1) * 16)) + GMAT;

  float c[4][4][4] = {};
  const int NK = K / 16;

  uint4 pah, pal, pbh, pbl;
  pah = *(const uint4*)(Ahi + arow);  pal = *(const uint4*)(Alo + arow);
  pbh = *(const uint4*)(Bhi + brow);  pbl = *(const uint4*)(Blo + brow);
  *(uint4*)(smc + stOff)               = pah;
  *(uint4*)(smc + stOff + 32)          = pal;
  *(uint4*)(smc + GMAT + stOff)        = pbh;
  *(uint4*)(smc + GMAT + stOff + 32)   = pbl;
  __syncthreads();

  for (int kc = 0; kc < NK; kc++) {
    const int s = kc & 1;
    if (kc + 1 < NK) {
      pah = *(const uint4*)(Ahi + arow + (kc + 1) * 16);
      pal = *(const uint4*)(Alo + arow + (kc + 1) * 16);
      pbh = *(const uint4*)(Bhi + brow + (kc + 1) * 16);
      pbl = *(const uint4*)(Blo + brow + (kc + 1) * 16);
    }

    const uint32_t stg = sb + s * GSTAGE;
    uint32_t ahi[4][4], alo[4][4], bhi[2][4], blo[2][4];
    #pragma unroll
    for (int mt = 0; mt < 4; mt++) {
      uint32_t ad = stg + aoff + mt * (16 * GPITCH);
      LDSM4(ahi[mt][0], ahi[mt][1], ahi[mt][2], ahi[mt][3], ad);
      LDSM4(alo[mt][0], alo[mt][1], alo[mt][2], alo[mt][3], ad + 32);
    }
    #pragma unroll
    for (int g = 0; g < 2; g++) {
      uint32_t bd = stg + boff + g * (16 * GPITCH);
      LDSM4(bhi[g][0], bhi[g][1], bhi[g][2], bhi[g][3], bd);
      LDSM4(blo[g][0], blo[g][1], blo[g][2], blo[g][3], bd + 32);
    }

    #pragma unroll
    for (int mt = 0; mt < 4; mt++) {
      #pragma unroll
      for (int nt = 0; nt < 4; nt++) {
        const int g = nt >> 1, q = (nt & 1) * 2;
        MMA16816(c[mt][nt], ahi[mt][0], ahi[mt][1], ahi[mt][2], ahi[mt][3], bhi[g][q], bhi[g][q + 1]);
        MMA16816(c[mt][nt], ahi[mt][0], ahi[mt][1], ahi[mt][2], ahi[mt][3], blo[g][q], blo[g][q + 1]);
        MMA16816(c[mt][nt], alo[mt][0], alo[mt][1], alo[mt][2], alo[mt][3], bhi[g][q], bhi[g][q + 1]);
      }
    }

    if (kc + 1 < NK) {
      char* dst = smc + ((kc + 1) & 1) * GSTAGE + stOff;
      *(uint4*)(dst)             = pah;
      *(uint4*)(dst + 32)        = pal;
      *(uint4*)(dst + GMAT)      = pbh;
      *(uint4*)(dst + GMAT + 32) = pbl;
    }
    __syncthreads();
  }

  #pragma unroll
  for (int mt = 0; mt < 4; mt++) {
    const int row = m0 + wm + mt * 16 + (lane >> 2);
    #pragma unroll
    for (int nt = 0; nt < 4; nt++) {
      const int col = n0 + wn + nt * 8 + (lane & 3) * 2;
      float bx = 0.f, by = 0.f;
      if (bias) { bx = __ldg(&bias[col]); by = __ldg(&bias[col + 1]); }
      *(float2*)&Cout[(size_t)row * N + col] =
          make_float2(c[mt][nt][0] + bx, c[mt][nt][1] + by);
      *(float2*)&Cout[(size_t)(row + 8) * N + col] =
          make_float2(c[mt][nt][2] + bx, c[mt][nt][3] + by);
    }
  }
}

// ---------------- gate logits ----------------
__global__ __launch_bounds__(256) void gate_logits(
    const float* __restrict__ x, const float* __restrict__ Wa, const float* __restrict__ ba)
{
  __shared__ float sW[Hh * Cc];
  const int t = threadIdx.x;
  for (int i = t; i < Hh * Cc; i += 256) sW[i] = Wa[i];
  __syncthreads();

  const int warp = t >> 5, lane = t & 31;
  const int row = blockIdx.x * 8 + warp;
  const float* xr = x + (size_t)row * Cc;

  float acc[Hh] = {};
  for (int c0 = 0; c0 < Cc; c0 += 32) {
    float xv = xr[c0 + lane];
    #pragma unroll
    for (int h = 0; h < Hh; h++) acc[h] += xv * sW[h * Cc + c0 + lane];
  }
  #pragma unroll
  for (int h = 0; h < Hh; h++) {
    float v = acc[h];
    #pragma unroll
    for (int o = 16; o; o >>= 1) v += __shfl_xor_sync(0xffffffffu, v, o);
    if (lane == 0) g_z[(size_t)row * Hh + h] = v + ba[h];
  }
}

// ---------------- per-(b,h) scan ----------------
__global__ __launch_bounds__(1024) void gate_scan()
{
  __shared__ float sh[1024];
  const int bh = blockIdx.x;
  const int b = bh / Hh, h = bh % Hh;
  const int t = threadIdx.x;

  float la = 0.f;
  if (t > 0) {
    float z = g_z[((size_t)b * Nn + t) * Hh + h];
    float sp = (z > 15.f) ? z : log1pf(__expf(z));   // softplus
    la = -sp;
  }
  sh[t] = la;
  __syncthreads();
  #pragma unroll
  for (int off = 1; off < 1024; off <<= 1) {
    float v = (t >= off) ? sh[t - off] : 0.f;
    __syncthreads();
    sh[t] += v;
    __syncthreads();
  }
  float* cp = g_c + (size_t)bh * (Nn + 1);
  if (t == 0) cp[0] = 0.f;
  cp[t + 1] = sh[t];
}

// -------- qkv split: q/k silu+0.5+L2norm, v pass-through; write bf16 hi/lo planes --------
__global__ __launch_bounds__(256) void qkv_split()
{
  const int bn = blockIdx.x;                  // 0..2047
  const int warp = threadIdx.x >> 5, lane = threadIdx.x & 31;
  const size_t rowoff = (size_t)bn * 3 * Cc;

  for (int task = warp; task < 3 * Hh; task += 8) {
    const int s = task % 3, h = task / 3;
    const size_t seg = rowoff + s * Cc + h * Dd;
    const float* p = g_qkv + seg;
    float v0 = p[2 * lane], v1 = p[2 * lane + 1];
    float r0 = v0, r1 = v1;
    if (s < 2) {
      r0 = v0 / (1.f + __expf(-v0)) + 0.5f;
      r1 = v1 / (1.f + __expf(-v1)) + 0.5f;
      float ss = r0 * r0 + r1 * r1;
      #pragma unroll
      for (int o = 16; o; o >>= 1) ss += __shfl_xor_sync(0xffffffffu, ss, o);
      float inv = rsqrtf(ss);
      r0 *= inv; r1 *= inv;
    }
    __nv_bfloat162 hb = __floats2bfloat162_rn(r0, r1);
    float2 hf = __bfloat1622float2(hb);
    __nv_bfloat162 lb = __floats2bfloat162_rn(r0 - hf.x, r1 - hf.y);
    *(__nv_bfloat162*)(g_hi + seg + 2 * lane) = hb;
    *(__nv_bfloat162*)(g_lo + seg + 2 * lane) = lb;
  }
}

// ================= attention: register-resident S + dead-tile skipping ==================
#define APITCH 144
#define AMAT   (64 * APITCH)   // 9216
#define O_QHI  0
#define O_QLO  (O_QHI + AMAT)
#define O_KHI  (O_QLO + AMAT)
#define O_KLO  (O_KHI + AMAT)
#define O_VHI  (O_KLO + AMAT)
#define O_VLO  (O_VHI + AMAT)
#define O_CI   (O_VLO + AMAT)
#define O_CI1  (O_CI  + 256)
#define O_CJ   (O_CI1 + 256)
#define O_CJ1  (O_CJ  + 256)
#define O_FI   (O_CJ1 + 256)
#define O_G    (O_FI  + 256)
#define O_H    (O_G   + 256)
#define O_RS   (O_H   + 256)
#define ASMEM  (O_RS + 64 * 8 * 4)   // 59136

__global__ __launch_bounds__(256, 2) void attn_kernel(
    const __nv_bfloat16* __restrict__ hip, const __nv_bfloat16* __restrict__ lop,
    const float* __restrict__ cbuf)
{
  extern __shared__ char smc[];
  const uint32_t sb = smem_u32(smc);
  float* ci  = (float*)(smc + O_CI);
  float* ci1 = (float*)(smc + O_CI1);
  float* cj  = (float*)(smc + O_CJ);
  float* cj1 = (float*)(smc + O_CJ1);
  float* sFi = (float*)(smc + O_FI);
  float* sG  = (float*)(smc + O_G);
  float* sH  = (float*)(smc + O_H);
  float* rs  = (float*)(smc + O_RS);

  const int bh = blockIdx.x;
  const int b = bh / Hh, h = bh % Hh;
  const int by = blockIdx.y;
  const int i0 = by * 64;
  const int tid = threadIdx.x, wid = tid >> 5, lane = tid & 31;
  const int wm = (wid & 3) * 16;        // i-row group
  const int wn = (wid >> 2) * 32;       // j-half

  const float* cb = cbuf + (size_t)bh * (Nn + 1);
  const __nv_bfloat16* hrow = hip + (size_t)b * Nn * 3 * Cc + h * Dd;
  const __nv_bfloat16* lrow = lop + (size_t)b * Nn * 3 * Cc + h * Dd;

  const int mrow = tid >> 2, lq = tid & 3;
  const size_t kq = Cc + (size_t)mrow * 3 * Cc + lq * 16;
  const size_t vq = 2 * Cc + (size_t)mrow * 3 * Cc + lq * 16;

  // stage Q (once) from planes
  {
    const size_t qo = (size_t)(i0 + mrow) * 3 * Cc + lq * 16;
    const uint4* qh4 = (const uint4*)(hrow + qo);
    const uint4* ql4 = (const uint4*)(lrow + qo);
    *(uint4*)(smc + O_QHI + mrow * APITCH + lq * 32)      = qh4[0];
    *(uint4*)(smc + O_QHI + mrow * APITCH + lq * 32 + 16) = qh4[1];
    *(uint4*)(smc + O_QLO + mrow * APITCH + lq * 32)      = ql4[0];
    *(uint4*)(smc + O_QLO + mrow * APITCH + lq * 32 + 16) = ql4[1];
  }
  if (tid < 64) {
    ci[tid]  = cb[i0 + tid];
    ci1[tid] = cb[i0 + tid + 1];
    sFi[tid] = __expf(cb[i0 + tid] - cb[i0]);
  }

  // active-tile list (uniform across threads; c is monotone non-increasing)
  int act[16], nact = 0;
  {
    const float ctop = cb[i0], cbot = cb[i0 + 64];
    #pragma unroll
    for (int jt = 0; jt < 16; jt++) {
      bool on;
      if (jt == by)      on = true;
      else if (jt < by)  on = (ctop - cb[jt * 64 + 63]) > SKIP_LOG;
      else               on = (cb[jt * 64 + 1] - cbot) > SKIP_LOG;
      if (on) act[nact++] = jt;
    }
  }
  __syncthreads();

  const uint32_t aoff = (uint32_t)((wm + (lane & 15)) * APITCH + ((lane >> 4) * 16));
  uint32_t qh[4][4];
  #pragma unroll
  for (int k = 0; k < 4; k++)
    LDSM4(qh[k][0], qh[k][1], qh[k][2], qh[k][3], sb + O_QHI + aoff + k * 32);

  const uint32_t boff = (uint32_t)((wn + ((lane >> 4) << 3) + (lane & 7)) * APITCH
                                   + (((lane >> 3) & 1) * 16));
  const uint32_t voff = (uint32_t)((wn + (lane & 15)) * APITCH + ((lane >> 4) * 16));

  float acc[8][4] = {};
  float rsum0 = 0.f, rsum1 = 0.f;

  uint4 pk[4], pv[4];
  {
    const size_t off = (size_t)(act[0] * 64) * 3 * Cc;
    pk[0] = *(const uint4*)(hrow + kq + off);  pk[1] = *(const uint4*)(hrow + kq + off + 8);
    pk[2] = *(const uint4*)(lrow + kq + off);  pk[3] = *(const uint4*)(lrow + kq + off + 8);
    pv[0] = *(const uint4*)(hrow + vq + off);  pv[1] = *(const uint4*)(hrow + vq + off + 8);
    pv[2] = *(const uint4*)(lrow + vq + off);  pv[3] = *(const uint4*)(lrow + vq + off + 8);
  }

  for (int a = 0; a < nact; a++) {
    const int jt = act[a];
    const int j0 = jt * 64;
    __syncthreads();

    {
      const uint32_t base = (uint32_t)(mrow * APITCH + lq * 32);
      *(uint4*)(smc + O_KHI + base)      = pk[0];
      *(uint4*)(smc + O_KHI + base + 16) = pk[1];
      *(uint4*)(smc + O_KLO + base)      = pk[2];
      *(uint4*)(smc + O_KLO + base + 16) = pk[3];
      *(uint4*)(smc + O_VHI + base)      = pv[0];
      *(uint4*)(smc + O_VHI + base + 16) = pv[1];
      *(uint4*)(smc + O_VLO + base)      = pv[2];
      *(uint4*)(smc + O_VLO + base + 16) = pv[3];
    }
    if (jt == by) {
      if (tid < 64) { cj[tid] = cb[j0 + tid]; cj1[tid] = cb[j0 + tid + 1]; }
    } else if (jt < by) {
      if (tid < 64) sG[tid] = __expf(cb[i0] - cb[j0 + tid]);
    } else {
      if (tid < 64)        sG[tid]       = __expf(cb[j0 + tid + 1] - cb[j0]);
      else if (tid < 128)  sH[tid - 64]  = __expf(cb[j0] - cb[i0 + (tid - 64) + 1]);
    }
    __syncthreads();

    if (a + 1 < nact) {
      const size_t off = (size_t)(act[a + 1] * 64) * 3 * Cc;
      pk[0] = *(const uint4*)(hrow + kq + off);  pk[1] = *(const uint4*)(hrow + kq + off + 8);
      pk[2] = *(const uint4*)(lrow + kq + off);  pk[3] = *(const uint4*)(lrow + kq + off + 8);
      pv[0] = *(const uint4*)(hrow + vq + off);  pv[1] = *(const uint4*)(hrow + vq + off + 8);
      pv[2] = *(const uint4*)(lrow + vq + off);  pv[3] = *(const uint4*)(lrow + vq + off + 8);
    }

    // ---- phase A: S = Q.K^T (3-pass), S[16x32] in regs ----
    float s[4][4] = {};
    #pragma unroll
    for (int k = 0; k < 4; k++) {
      uint32_t qlr[4];
      LDSM4(qlr[0], qlr[1], qlr[2], qlr[3], sb + O_QLO + aoff + k * 32);
      uint32_t bd0 = sb + O_KHI + boff + k * 32;
      uint32_t bd1 = bd0 + 16 * APITCH;
      uint32_t kh0[4], kl0[4], kh1[4], kl1[4];
      LDSM4(kh0[0], kh0[1], kh0[2], kh0[3], bd0);
      LDSM4(kl0[0], kl0[1], kl0[2], kl0[3], bd0 + AMAT);
      LDSM4(kh1[0], kh1[1], kh1[2], kh1[3], bd1);
      LDSM4(kl1[0], kl1[1], kl1[2], kl1[3], bd1 + AMAT);
      #pragma unroll
      for (int nt = 0; nt < 4; nt++) {
        const uint32_t* KH = (nt < 2) ? kh0 : kh1;
        const uint32_t* KL = (nt < 2) ? kl0 : kl1;
        const int q = (nt & 1) * 2;
        MMA16816(s[nt], qh[k][0], qh[k][1], qh[k][2], qh[k][3], KH[q], KH[q + 1]);
        MMA16816(s[nt], qh[k][0], qh[k][1], qh[k][2], qh[k][3], KL[q], KL[q + 1]);
        MMA16816(s[nt], qlr[0], qlr[1], qlr[2], qlr[3], KH[q], KH[q + 1]);
      }
    }

    // ---- mask + rowsum (registers) ----
    const int r0l = wm + (lane >> 2);
    const int r1l = r0l + 8;
    if (jt == by) {
      #pragma unroll
      for (int nt = 0; nt < 4; nt++) {
        const int jl = wn + nt * 8 + (lane & 3) * 2;
        #pragma unroll
        for (int e = 0; e < 4; e++) {
          const int il = (e < 2) ? r0l : r1l;
          const int jj = jl + (e & 1);
          const int ig = i0 + il, jg = j0 + jj;
          float arg = (jg < ig) ? (ci[il] - cj[jj]) : ((jg > ig) ? (cj1[jj] - ci1[il]) : 0.f);
          s[nt][e] = s[nt][e] * ATT_SCALE * __expf(arg);
        }
      }
    } else {
      const float* rf = (jt < by) ? sFi : sH;
      const float f0 = ATT_SCALE * rf[r0l];
      const float f1 = ATT_SCALE * rf[r1l];
      #pragma unroll
      for (int nt = 0; nt < 4; nt++) {
        const int jl = wn + nt * 8 + (lane & 3) * 2;
        const float g0 = sG[jl], g1 = sG[jl + 1];
        s[nt][0] *= f0 * g0; s[nt][1] *= f0 * g1;
        s[nt][2] *= f1 * g0; s[nt][3] *= f1 * g1;
      }
    }
    #pragma unroll
    for (int nt = 0; nt < 4; nt++) {
      rsum0 += s[nt][0] + s[nt][1];
      rsum1 += s[nt][2] + s[nt][3];
    }

    // ---- phase B: partial out += S.V over this warp's j-half (S stays in regs) ----
    #pragma unroll
    for (int kk = 0; kk < 2; kk++) {
      uint32_t shA[4], slA[4];
      #pragma unroll
      for (int p = 0; p < 4; p++) {
        const float x0 = s[2 * kk + (p >> 1)][(p & 1) * 2];
        const float x1 = s[2 * kk + (p >> 1)][(p & 1) * 2 + 1];
        __nv_bfloat162 hb = __floats2bfloat162_rn(x0, x1);
        float2 hf = __bfloat1622float2(hb);
        __nv_bfloat162 lb = __floats2bfloat162_rn(x0 - hf.x, x1 - hf.y);
        shA[p] = *(uint32_t*)&hb;
        slA[p] = *(uint32_t*)&lb;
      }
      #pragma unroll
      for (int dseg = 0; dseg < 4; dseg++) {
        uint32_t va = sb + O_VHI + voff + (uint32_t)(kk * 16 * APITCH + dseg * 32);
        uint32_t vh[4], vl[4];
        LDSM4T(vh[0], vh[1], vh[2], vh[3], va);
        LDSM4T(vl[0], vl[1], vl[2], vl[3], va + AMAT);
        #pragma unroll
        for (int t2 = 0; t2 < 2; t2++) {
          const int nt = dseg * 2 + t2;
          const int q = t2 * 2;
          MMA16816(acc[nt], shA[0], shA[1], shA[2], shA[3], vh[q], vh[q + 1]);
          MMA16816(acc[nt], shA[0], shA[1], shA[2], shA[3], vl[q], vl[q + 1]);
          MMA16816(acc[nt], slA[0], slA[1], slA[2], slA[3], vh[q], vh[q + 1]);
        }
      }
    }
  }

  // ---- epilogue: rowsum reduce + cross-warp j-half sum + normalize + write planes ----
  __syncthreads();
  {
    const int r0l = wm + (lane >> 2);
    const int slot = (wid >> 2) * 4 + (lane & 3);
    rs[r0l * 8 + slot]       = rsum0;
    rs[(r0l + 8) * 8 + slot] = rsum1;
  }
  float* xch = (float*)(smc + O_KHI);   // [64][68] partial-out exchange
  if (wid >= 4) {
    const int r0l = wm + (lane >> 2), r1l = r0l + 8;
    #pragma unroll
    for (int nt = 0; nt < 8; nt++) {
      const int col = nt * 8 + (lane & 3) * 2;
      *(float2*)&xch[r0l * 68 + col] = make_float2(acc[nt][0], acc[nt][1]);
      *(float2*)&xch[r1l * 68 + col] = make_float2(acc[nt][2], acc[nt][3]);
    }
  }
  __syncthreads();
  if (wid < 4) {
    const int r0l = wm + (lane >> 2), r1l = r0l + 8;
    float t0 = 0.f, t1 = 0.f;
    #pragma unroll
    for (int g = 0; g < 8; g++) { t0 += rs[r0l * 8 + g]; t1 += rs[r1l * 8 + g]; }
    const float inv0 = 1.f / (t0 + 1e-6f);
    const float inv1 = 1.f / (t1 + 1e-6f);
    #pragma unroll
    for (int nt = 0; nt < 8; nt++) {
      const int col = nt * 8 + (lane & 3) * 2;
      float2 p0 = *(float2*)&xch[r0l * 68 + col];
      float2 p1 = *(float2*)&xch[r1l * 68 + col];
      float o00 = (acc[nt][0] + p0.x) * inv0, o01 = (acc[nt][1] + p0.y) * inv0;
      float o10 = (acc[nt][2] + p1.x) * inv1, o11 = (acc[nt][3] + p1.y) * inv1;
      const size_t a0 = ((size_t)(b * Nn + i0 + r0l)) * Cc + h * Dd + col;
      const size_t a1 = ((size_t)(b * Nn + i0 + r1l)) * Cc + h * Dd + col;
      __nv_bfloat162 hb; float2 hf; __nv_bfloat162 lb;
      hb = __floats2bfloat162_rn(o00, o01); hf = __bfloat1622float2(hb);
      lb = __floats2bfloat162_rn(o00 - hf.x, o01 - hf.y);
      *(uint32_t*)(g_aohi + a0) = *(uint32_t*)&hb;
      *(uint32_t*)(g_aolo + a0) = *(uint32_t*)&lb;
      hb = __floats2bfloat162_rn(o10, o11); hf = __bfloat1622float2(hb);
      lb = __floats2bfloat162_rn(o10 - hf.x, o11 - hf.y);
      *(uint32_t*)(g_aohi + a1) = *(uint32_t*)&hb;
      *(uint32_t*)(g_aolo + a1) = *(uint32_t*)&lb;
    }
  }
}

// ---------------- launch ----------------
extern "C" void kernel_launch(void* const* d_in, const int* in_sizes, int n_in,
                              void* d_out, int out_size)
{
  const float* x     = (const float*)d_in[0];
  const float* Wqkv  = (const float*)d_in[1];
  const float* Wa    = (const float*)d_in[2];
  const float* ba    = (const float*)d_in[3];
  const float* Wproj = (const float*)d_in[4];
  const float* bproj = (const float*)d_in[5];
  float* out = (float*)d_out;

  float *qkv, *cbuf;
  __nv_bfloat16 *hip, *lop, *xhi, *xlo, *w1hi, *w1lo, *w2hi, *w2lo, *aohi, *aolo;
  cudaGetSymbolAddress((void**)&qkv,  g_qkv);
  cudaGetSymbolAddress((void**)&cbuf, g_c);
  cudaGetSymbolAddress((void**)&hip,  g_hi);
  cudaGetSymbolAddress((void**)&lop,  g_lo);
  cudaGetSymbolAddress((void**)&xhi,  g_xhi);   cudaGetSymbolAddress((void**)&xlo,  g_xlo);
  cudaGetSymbolAddress((void**)&w1hi, g_w1hi);  cudaGetSymbolAddress((void**)&w1lo, g_w1lo);
  cudaGetSymbolAddress((void**)&w2hi, g_w2hi);  cudaGetSymbolAddress((void**)&w2lo, g_w2lo);
  cudaGetSymbolAddress((void**)&aohi, g_aohi);  cudaGetSymbolAddress((void**)&aolo, g_aolo);

  cudaFuncSetAttribute(attn_kernel, cudaFuncAttributeMaxDynamicSharedMemorySize, ASMEM);
  cudaFuncSetAttribute(gemm_mma, cudaFuncAttributeMaxDynamicSharedMemorySize, GSMEM);

  // 0) split x / Wqkv / Wproj into bf16 hi/lo planes
  const int nx = Bb * Nn * Cc, nw1 = 3 * Cc * Cc, nw2 = Cc * Cc;
  split_planes<<<(nx  / 4 + 255) / 256, 256>>>(x,     xhi,  xlo,  nx);
  split_planes<<<(nw1 / 4 + 255) / 256, 256>>>(Wqkv,  w1hi, w1lo, nw1);
  split_planes<<<(nw2 / 4 + 255) / 256, 256>>>(Wproj, w2hi, w2lo, nw2);
  // 1) qkv = x @ Wqkv^T (bf16 mma, 3-pass, plane inputs, 2 CTAs/SM)
  gemm_mma<<<dim3(3 * Cc / 128, Bb * Nn / 128), 256, GSMEM>>>(
      xhi, xlo, w1hi, w1lo, nullptr, qkv, Bb * Nn, 3 * Cc, Cc);
  // 2) gate logits
  gate_logits<<<Bb * Nn / 8, 256>>>(x, Wa, ba);
  // 3) prefix-sum of log gates per (b,h)
  gate_scan<<<Bb * Hh, 1024>>>();
  // 4) q/k norm + split qkv into bf16 hi/lo planes
  qkv_split<<<Bb * Nn, 256>>>();
  // 5) attention (register-resident S + dead-tile skipping; writes ao planes)
  attn_kernel<<<dim3(Bb * Hh, Nn / 64), 256, ASMEM>>>(hip, lop, cbuf);
  // 6) out = ao @ Wproj^T + bproj (plane inputs)
  gemm_mma<<<dim3(Cc / 128, Bb * Nn / 128), 256, GSMEM>>>(
      aohi, aolo, w2hi, w2lo, bproj, out, Bb * Nn, Cc, Cc);
}

// round 12
// speedup vs baseline: 1.0256x; 1.0256x over previous
#include <cuda_runtime.h>
#include <cuda_bf16.h>
#include <math.h>
#include <cstdint>

#define Bb 2
#define Nn 1024
#define Cc 768
#define Hh 12
#define Dd 64
#define ATT_SCALE 0.125f   // D^-0.5
#define SKIP_LOG  -30.0f   // tiles with max log-mask below this contribute < 1e-12 relative

// ---------------- scratch (static device memory; no allocations) ----------------
__device__ float g_qkv[Bb * Nn * 3 * Cc];            // fp32 qkv from GEMM
__device__ __nv_bfloat16 g_hi[Bb * Nn * 3 * Cc];     // qkv planes (q/k normalized, v raw)
__device__ __nv_bfloat16 g_lo[Bb * Nn * 3 * Cc];
__device__ __nv_bfloat16 g_xhi[Bb * Nn * Cc],  g_xlo[Bb * Nn * Cc];     // x planes
__device__ __nv_bfloat16 g_w1hi[3 * Cc * Cc],  g_w1lo[3 * Cc * Cc];     // Wqkv planes
__device__ __nv_bfloat16 g_w2hi[Cc * Cc],      g_w2lo[Cc * Cc];         // Wproj planes
__device__ __nv_bfloat16 g_aohi[Bb * Nn * Cc], g_aolo[Bb * Nn * Cc];    // attn out planes
__device__ float g_z  [Bb * Nn * Hh];                // gate logits
__device__ float g_c  [Bb * Hh * (Nn + 1)];          // prefix sums of log a

__device__ __forceinline__ uint32_t smem_u32(const void* p) {
  uint32_t a;
  asm("{ .reg .u64 t; cvta.to.shared.u64 t, %1; cvt.u32.u64 %0, t; }" : "=r"(a) : "l"(p));
  return a;
}

#define LDSM4(R0, R1, R2, R3, addr) \
  asm volatile("ldmatrix.sync.aligned.m8n8.x4.shared.b16 {%0,%1,%2,%3}, [%4];" \
               : "=r"(R0), "=r"(R1), "=r"(R2), "=r"(R3) : "r"(addr))

#define LDSM4T(R0, R1, R2, R3, addr) \
  asm volatile("ldmatrix.sync.aligned.m8n8.x4.trans.shared.b16 {%0,%1,%2,%3}, [%4];" \
               : "=r"(R0), "=r"(R1), "=r"(R2), "=r"(R3) : "r"(addr))

#define MMA16816(C, A0, A1, A2, A3, B0, B1) \
  asm volatile("mma.sync.aligned.m16n8k16.row.col.f32.bf16.bf16.f32 " \
               "{%0,%1,%2,%3}, {%4,%5,%6,%7}, {%8,%9}, {%0,%1,%2,%3};" \
               : "+f"((C)[0]), "+f"((C)[1]), "+f"((C)[2]), "+f"((C)[3]) \
               : "r"(A0), "r"(A1), "r"(A2), "r"(A3), "r"(B0), "r"(B1))

#define CP16(dst, src) \
  asm volatile("cp.async.cg.shared.global [%0], [%1], 16;" :: "r"(dst), "l"(src))
#define CP_COMMIT() asm volatile("cp.async.commit_group;" ::: "memory")
#define CP_WAIT1()  asm volatile("cp.async.wait_group 1;" ::: "memory")

// ---------------- generic fp32 -> bf16 hi/lo plane split (vectorized x4) ----------------
__global__ __launch_bounds__(256) void split_planes(
    const float* __restrict__ src, __nv_bfloat16* __restrict__ hi,
    __nv_bfloat16* __restrict__ lo, int n)
{
  const int i = (blockIdx.x * 256 + threadIdx.x) * 4;
  if (i >= n) return;
  float4 v = *(const float4*)(src + i);
  __nv_bfloat162 h0 = __floats2bfloat162_rn(v.x, v.y);
  float2 f0 = __bfloat1622float2(h0);
  __nv_bfloat162 l0 = __floats2bfloat162_rn(v.x - f0.x, v.y - f0.y);
  __nv_bfloat162 h1 = __floats2bfloat162_rn(v.z, v.w);
  float2 f1 = __bfloat1622float2(h1);
  __nv_bfloat162 l1 = __floats2bfloat162_rn(v.z - f1.x, v.w - f1.y);
  *(uint2*)(hi + i) = make_uint2(*(uint32_t*)&h0, *(uint32_t*)&h1);
  *(uint2*)(lo + i) = make_uint2(*(uint32_t*)&l0, *(uint32_t*)&l1);
}

// ===== tensor-core GEMM (bf16 3-pass, plane inputs, cp.async 3-stage): C = A @ B^T (+bias)
#define GPITCH 80
#define GMAT   (128 * GPITCH)      // 10240
#define GSTAGE (2 * GMAT)          // 20480
#define GSMEM  (3 * GSTAGE)        // 61440

__global__ __launch_bounds__(256, 2) void gemm_mma(
    const __nv_bfloat16* __restrict__ Ahi, const __nv_bfloat16* __restrict__ Alo,
    const __nv_bfloat16* __restrict__ Bhi, const __nv_bfloat16* __restrict__ Blo,
    const float* __restrict__ bias, float* __restrict__ Cout,
    int M, int N, int K)
{
  extern __shared__ char smc[];
  const uint32_t sb = smem_u32(smc);
  const int tid = threadIdx.x, wid = tid >> 5, lane = tid & 31;
  const int m0 = blockIdx.y * 128, n0 = blockIdx.x * 128;
  const int wm = (wid & 1) * 64, wn = (wid >> 1) * 32;

  const int lrow = tid >> 1;
  const size_t arow = (size_t)(m0 + lrow) * K + (tid & 1) * 8;
  const size_t brow = (size_t)(n0 + lrow) * K + (tid & 1) * 8;
  const __nv_bfloat16* Ah = Ahi + arow;
  const __nv_bfloat16* Al = Alo + arow;
  const __nv_bfloat16* Bh = Bhi + brow;
  const __nv_bfloat16* Bl = Blo + brow;
  const uint32_t stOff = sb + (uint32_t)(lrow * GPITCH + (tid & 1) * 16);   // hi; lo at +32

  const uint32_t aoff = (uint32_t)((wm + (lane & 15)) * GPITCH + ((lane >> 4) * 16));
  const uint32_t boff = (uint32_t)((wn + ((lane >> 4) << 3) + (lane & 7)) * GPITCH
                                   + (((lane >> 3) & 1) * 16)) + GMAT;

  float c[4][4][4] = {};
  const int NK = K / 16;

  // prologue: issue chunks 0 and 1 into stages 0,1
  {
    CP16(stOff,              Ah);
    CP16(stOff + 32,         Al);
    CP16(stOff + GMAT,       Bh);
    CP16(stOff + GMAT + 32,  Bl);
    CP_COMMIT();
    CP16(stOff + GSTAGE,             Ah + 16);
    CP16(stOff + GSTAGE + 32,        Al + 16);
    CP16(stOff + GSTAGE + GMAT,      Bh + 16);
    CP16(stOff + GSTAGE + GMAT + 32, Bl + 16);
    CP_COMMIT();
  }

  int stage = 0;                 // stage holding chunk kc
  for (int kc = 0; kc < NK; kc++) {
    CP_WAIT1();                  // chunk kc has landed
    __syncthreads();             // all warps see it; all warps done reading stage (kc-1)%3

    // issue chunk kc+2 into stage (kc+2)%3 == (kc-1)%3 (drained by the barrier above)
    if (kc + 2 < NK) {
      const int ns = (stage + 2 == 3) ? 2 : ((stage + 2) % 3);
      const uint32_t d = stOff + (uint32_t)(((stage + 2) % 3) * GSTAGE);
      (void)ns;
      const int ko = (kc + 2) * 16;
      CP16(d,             Ah + ko);
      CP16(d + 32,        Al + ko);
      CP16(d + GMAT,      Bh + ko);
      CP16(d + GMAT + 32, Bl + ko);
    }
    CP_COMMIT();                 // commit (possibly empty) to keep group accounting uniform

    const uint32_t stg = sb + (uint32_t)(stage * GSTAGE) - sb + sb;   // = sb + stage*GSTAGE
    const uint32_t base = sb + (uint32_t)(stage * GSTAGE);
    (void)stg;
    uint32_t ahi[4][4], alo[4][4], bhi[2][4], blo[2][4];
    #pragma unroll
    for (int mt = 0; mt < 4; mt++) {
      uint32_t ad = base + aoff + mt * (16 * GPITCH);
      LDSM4(ahi[mt][0], ahi[mt][1], ahi[mt][2], ahi[mt][3], ad);
      LDSM4(alo[mt][0], alo[mt][1], alo[mt][2], alo[mt][3], ad + 32);
    }
    #pragma unroll
    for (int g = 0; g < 2; g++) {
      uint32_t bd = base + boff + g * (16 * GPITCH);
      LDSM4(bhi[g][0], bhi[g][1], bhi[g][2], bhi[g][3], bd);
      LDSM4(blo[g][0], blo[g][1], blo[g][2], blo[g][3], bd + 32);
    }

    #pragma unroll
    for (int mt = 0; mt < 4; mt++) {
      #pragma unroll
      for (int nt = 0; nt < 4; nt++) {
        const int g = nt >> 1, q = (nt & 1) * 2;
        MMA16816(c[mt][nt], ahi[mt][0], ahi[mt][1], ahi[mt][2], ahi[mt][3], bhi[g][q], bhi[g][q + 1]);
        MMA16816(c[mt][nt], ahi[mt][0], ahi[mt][1], ahi[mt][2], ahi[mt][3], blo[g][q], blo[g][q + 1]);
        MMA16816(c[mt][nt], alo[mt][0], alo[mt][1], alo[mt][2], alo[mt][3], bhi[g][q], bhi[g][q + 1]);
      }
    }

    stage = (stage + 1 == 3) ? 0 : stage + 1;
  }

  #pragma unroll
  for (int mt = 0; mt < 4; mt++) {
    const int row = m0 + wm + mt * 16 + (lane >> 2);
    #pragma unroll
    for (int nt = 0; nt < 4; nt++) {
      const int col = n0 + wn + nt * 8 + (lane & 3) * 2;
      float bx = 0.f, by = 0.f;
      if (bias) { bx = __ldg(&bias[col]); by = __ldg(&bias[col + 1]); }
      *(float2*)&Cout[(size_t)row * N + col] =
          make_float2(c[mt][nt][0] + bx, c[mt][nt][1] + by);
      *(float2*)&Cout[(size_t)(row + 8) * N + col] =
          make_float2(c[mt][nt][2] + bx, c[mt][nt][3] + by);
    }
  }
}

// ---------------- gate logits ----------------
__global__ __launch_bounds__(256) void gate_logits(
    const float* __restrict__ x, const float* __restrict__ Wa, const float* __restrict__ ba)
{
  __shared__ float sW[Hh * Cc];
  const int t = threadIdx.x;
  for (int i = t; i < Hh * Cc; i += 256) sW[i] = Wa[i];
  __syncthreads();

  const int warp = t >> 5, lane = t & 31;
  const int row = blockIdx.x * 8 + warp;
  const float* xr = x + (size_t)row * Cc;

  float acc[Hh] = {};
  for (int c0 = 0; c0 < Cc; c0 += 32) {
    float xv = xr[c0 + lane];
    #pragma unroll
    for (int h = 0; h < Hh; h++) acc[h] += xv * sW[h * Cc + c0 + lane];
  }
  #pragma unroll
  for (int h = 0; h < Hh; h++) {
    float v = acc[h];
    #pragma unroll
    for (int o = 16; o; o >>= 1) v += __shfl_xor_sync(0xffffffffu, v, o);
    if (lane == 0) g_z[(size_t)row * Hh + h] = v + ba[h];
  }
}

// ---------------- per-(b,h) scan ----------------
__global__ __launch_bounds__(1024) void gate_scan()
{
  __shared__ float sh[1024];
  const int bh = blockIdx.x;
  const int b = bh / Hh, h = bh % Hh;
  const int t = threadIdx.x;

  float la = 0.f;
  if (t > 0) {
    float z = g_z[((size_t)b * Nn + t) * Hh + h];
    float sp = (z > 15.f) ? z : log1pf(__expf(z));   // softplus
    la = -sp;
  }
  sh[t] = la;
  __syncthreads();
  #pragma unroll
  for (int off = 1; off < 1024; off <<= 1) {
    float v = (t >= off) ? sh[t - off] : 0.f;
    __syncthreads();
    sh[t] += v;
    __syncthreads();
  }
  float* cp = g_c + (size_t)bh * (Nn + 1);
  if (t == 0) cp[0] = 0.f;
  cp[t + 1] = sh[t];
}

// -------- qkv split: q/k silu+0.5+L2norm, v pass-through; write bf16 hi/lo planes --------
__global__ __launch_bounds__(256) void qkv_split()
{
  const int bn = blockIdx.x;                  // 0..2047
  const int warp = threadIdx.x >> 5, lane = threadIdx.x & 31;
  const size_t rowoff = (size_t)bn * 3 * Cc;

  for (int task = warp; task < 3 * Hh; task += 8) {
    const int s = task % 3, h = task / 3;
    const size_t seg = rowoff + s * Cc + h * Dd;
    const float* p = g_qkv + seg;
    float v0 = p[2 * lane], v1 = p[2 * lane + 1];
    float r0 = v0, r1 = v1;
    if (s < 2) {
      r0 = v0 / (1.f + __expf(-v0)) + 0.5f;
      r1 = v1 / (1.f + __expf(-v1)) + 0.5f;
      float ss = r0 * r0 + r1 * r1;
      #pragma unroll
      for (int o = 16; o; o >>= 1) ss += __shfl_xor_sync(0xffffffffu, ss, o);
      float inv = rsqrtf(ss);
      r0 *= inv; r1 *= inv;
    }
    __nv_bfloat162 hb = __floats2bfloat162_rn(r0, r1);
    float2 hf = __bfloat1622float2(hb);
    __nv_bfloat162 lb = __floats2bfloat162_rn(r0 - hf.x, r1 - hf.y);
    *(__nv_bfloat162*)(g_hi + seg + 2 * lane) = hb;
    *(__nv_bfloat162*)(g_lo + seg + 2 * lane) = lb;
  }
}

// ================= attention: register-resident S + dead-tile skipping ==================
#define APITCH 144
#define AMAT   (64 * APITCH)   // 9216
#define O_QHI  0
#define O_QLO  (O_QHI + AMAT)
#define O_KHI  (O_QLO + AMAT)
#define O_KLO  (O_KHI + AMAT)
#define O_VHI  (O_KLO + AMAT)
#define O_VLO  (O_VHI + AMAT)
#define O_CI   (O_VLO + AMAT)
#define O_CI1  (O_CI  + 256)
#define O_CJ   (O_CI1 + 256)
#define O_CJ1  (O_CJ  + 256)
#define O_FI   (O_CJ1 + 256)
#define O_G    (O_FI  + 256)
#define O_H    (O_G   + 256)
#define O_RS   (O_H   + 256)
#define ASMEM  (O_RS + 64 * 8 * 4)   // 59136

__global__ __launch_bounds__(256, 2) void attn_kernel(
    const __nv_bfloat16* __restrict__ hip, const __nv_bfloat16* __restrict__ lop,
    const float* __restrict__ cbuf)
{
  extern __shared__ char smc[];
  const uint32_t sb = smem_u32(smc);
  float* ci  = (float*)(smc + O_CI);
  float* ci1 = (float*)(smc + O_CI1);
  float* cj  = (float*)(smc + O_CJ);
  float* cj1 = (float*)(smc + O_CJ1);
  float* sFi = (float*)(smc + O_FI);
  float* sG  = (float*)(smc + O_G);
  float* sH  = (float*)(smc + O_H);
  float* rs  = (float*)(smc + O_RS);

  const int bh = blockIdx.x;
  const int b = bh / Hh, h = bh % Hh;
  const int by = blockIdx.y;
  const int i0 = by * 64;
  const int tid = threadIdx.x, wid = tid >> 5, lane = tid & 31;
  const int wm = (wid & 3) * 16;        // i-row group
  const int wn = (wid >> 2) * 32;       // j-half

  const float* cb = cbuf + (size_t)bh * (Nn + 1);
  const __nv_bfloat16* hrow = hip + (size_t)b * Nn * 3 * Cc + h * Dd;
  const __nv_bfloat16* lrow = lop + (size_t)b * Nn * 3 * Cc + h * Dd;

  const int mrow = tid >> 2, lq = tid & 3;
  const size_t kq = Cc + (size_t)mrow * 3 * Cc + lq * 16;
  const size_t vq = 2 * Cc + (size_t)mrow * 3 * Cc + lq * 16;

  // stage Q (once) from planes
  {
    const size_t qo = (size_t)(i0 + mrow) * 3 * Cc + lq * 16;
    const uint4* qh4 = (const uint4*)(hrow + qo);
    const uint4* ql4 = (const uint4*)(lrow + qo);
    *(uint4*)(smc + O_QHI + mrow * APITCH + lq * 32)      = qh4[0];
    *(uint4*)(smc + O_QHI + mrow * APITCH + lq * 32 + 16) = qh4[1];
    *(uint4*)(smc + O_QLO + mrow * APITCH + lq * 32)      = ql4[0];
    *(uint4*)(smc + O_QLO + mrow * APITCH + lq * 32 + 16) = ql4[1];
  }
  if (tid < 64) {
    ci[tid]  = cb[i0 + tid];
    ci1[tid] = cb[i0 + tid + 1];
    sFi[tid] = __expf(cb[i0 + tid] - cb[i0]);
  }

  // active-tile list (uniform across threads; c is monotone non-increasing)
  int act[16], nact = 0;
  {
    const float ctop = cb[i0], cbot = cb[i0 + 64];
    #pragma unroll
    for (int jt = 0; jt < 16; jt++) {
      bool on;
      if (jt == by)      on = true;
      else if (jt < by)  on = (ctop - cb[jt * 64 + 63]) > SKIP_LOG;
      else               on = (cb[jt * 64 + 1] - cbot) > SKIP_LOG;
      if (on) act[nact++] = jt;
    }
  }
  __syncthreads();

  const uint32_t aoff = (uint32_t)((wm + (lane & 15)) * APITCH + ((lane >> 4) * 16));
  uint32_t qh[4][4];
  #pragma unroll
  for (int k = 0; k < 4; k++)
    LDSM4(qh[k][0], qh[k][1], qh[k][2], qh[k][3], sb + O_QHI + aoff + k * 32);

  const uint32_t boff = (uint32_t)((wn + ((lane >> 4) << 3) + (lane & 7)) * APITCH
                                   + (((lane >> 3) & 1) * 16));
  const uint32_t voff = (uint32_t)((wn + (lane & 15)) * APITCH + ((lane >> 4) * 16));

  float acc[8][4] = {};
  float rsum0 = 0.f, rsum1 = 0.f;

  uint4 pk[4], pv[4];
  {
    const size_t off = (size_t)(act[0] * 64) * 3 * Cc;
    pk[0] = *(const uint4*)(hrow + kq + off);  pk[1] = *(const uint4*)(hrow + kq + off + 8);
    pk[2] = *(const uint4*)(lrow + kq + off);  pk[3] = *(const uint4*)(lrow + kq + off + 8);
    pv[0] = *(const uint4*)(hrow + vq + off);  pv[1] = *(const uint4*)(hrow + vq + off + 8);
    pv[2] = *(const uint4*)(lrow + vq + off);  pv[3] = *(const uint4*)(lrow + vq + off + 8);
  }

  for (int a = 0; a < nact; a++) {
    const int jt = act[a];
    const int j0 = jt * 64;
    __syncthreads();

    {
      const uint32_t base = (uint32_t)(mrow * APITCH + lq * 32);
      *(uint4*)(smc + O_KHI + base)      = pk[0];
      *(uint4*)(smc + O_KHI + base + 16) = pk[1];
      *(uint4*)(smc + O_KLO + base)      = pk[2];
      *(uint4*)(smc + O_KLO + base + 16) = pk[3];
      *(uint4*)(smc + O_VHI + base)      = pv[0];
      *(uint4*)(smc + O_VHI + base + 16) = pv[1];
      *(uint4*)(smc + O_VLO + base)      = pv[2];
      *(uint4*)(smc + O_VLO + base + 16) = pv[3];
    }
    if (jt == by) {
      if (tid < 64) { cj[tid] = cb[j0 + tid]; cj1[tid] = cb[j0 + tid + 1]; }
    } else if (jt < by) {
      if (tid < 64) sG[tid] = __expf(cb[i0] - cb[j0 + tid]);
    } else {
      if (tid < 64)        sG[tid]       = __expf(cb[j0 + tid + 1] - cb[j0]);
      else if (tid < 128)  sH[tid - 64]  = __expf(cb[j0] - cb[i0 + (tid - 64) + 1]);
    }
    __syncthreads();

    if (a + 1 < nact) {
      const size_t off = (size_t)(act[a + 1] * 64) * 3 * Cc;
      pk[0] = *(const uint4*)(hrow + kq + off);  pk[1] = *(const uint4*)(hrow + kq + off + 8);
      pk[2] = *(const uint4*)(lrow + kq + off);  pk[3] = *(const uint4*)(lrow + kq + off + 8);
      pv[0] = *(const uint4*)(hrow + vq + off);  pv[1] = *(const uint4*)(hrow + vq + off + 8);
      pv[2] = *(const uint4*)(lrow + vq + off);  pv[3] = *(const uint4*)(lrow + vq + off + 8);
    }

    // ---- phase A: S = Q.K^T (3-pass), S[16x32] in regs ----
    float s[4][4] = {};
    #pragma unroll
    for (int k = 0; k < 4; k++) {
      uint32_t qlr[4];
      LDSM4(qlr[0], qlr[1], qlr[2], qlr[3], sb + O_QLO + aoff + k * 32);
      uint32_t bd0 = sb + O_KHI + boff + k * 32;
      uint32_t bd1 = bd0 + 16 * APITCH;
      uint32_t kh0[4], kl0[4], kh1[4], kl1[4];
      LDSM4(kh0[0], kh0[1], kh0[2], kh0[3], bd0);
      LDSM4(kl0[0], kl0[1], kl0[2], kl0[3], bd0 + AMAT);
      LDSM4(kh1[0], kh1[1], kh1[2], kh1[3], bd1);
      LDSM4(kl1[0], kl1[1], kl1[2], kl1[3], bd1 + AMAT);
      #pragma unroll
      for (int nt = 0; nt < 4; nt++) {
        const uint32_t* KH = (nt < 2) ? kh0 : kh1;
        const uint32_t* KL = (nt < 2) ? kl0 : kl1;
        const int q = (nt & 1) * 2;
        MMA16816(s[nt], qh[k][0], qh[k][1], qh[k][2], qh[k][3], KH[q], KH[q + 1]);
        MMA16816(s[nt], qh[k][0], qh[k][1], qh[k][2], qh[k][3], KL[q], KL[q + 1]);
        MMA16816(s[nt], qlr[0], qlr[1], qlr[2], qlr[3], KH[q], KH[q + 1]);
      }
    }

    // ---- mask + rowsum (registers) ----
    const int r0l = wm + (lane >> 2);
    const int r1l = r0l + 8;
    if (jt == by) {
      #pragma unroll
      for (int nt = 0; nt < 4; nt++) {
        const int jl = wn + nt * 8 + (lane & 3) * 2;
        #pragma unroll
        for (int e = 0; e < 4; e++) {
          const int il = (e < 2) ? r0l : r1l;
          const int jj = jl + (e & 1);
          const int ig = i0 + il, jg = j0 + jj;
          float arg = (jg < ig) ? (ci[il] - cj[jj]) : ((jg > ig) ? (cj1[jj] - ci1[il]) : 0.f);
          s[nt][e] = s[nt][e] * ATT_SCALE * __expf(arg);
        }
      }
    } else {
      const float* rf = (jt < by) ? sFi : sH;
      const float f0 = ATT_SCALE * rf[r0l];
      const float f1 = ATT_SCALE * rf[r1l];
      #pragma unroll
      for (int nt = 0; nt < 4; nt++) {
        const int jl = wn + nt * 8 + (lane & 3) * 2;
        const float g0 = sG[jl], g1 = sG[jl + 1];
        s[nt][0] *= f0 * g0; s[nt][1] *= f0 * g1;
        s[nt][2] *= f1 * g0; s[nt][3] *= f1 * g1;
      }
    }
    #pragma unroll
    for (int nt = 0; nt < 4; nt++) {
      rsum0 += s[nt][0] + s[nt][1];
      rsum1 += s[nt][2] + s[nt][3];
    }

    // ---- phase B: partial out += S.V over this warp's j-half (S stays in regs) ----
    #pragma unroll
    for (int kk = 0; kk < 2; kk++) {
      uint32_t shA[4], slA[4];
      #pragma unroll
      for (int p = 0; p < 4; p++) {
        const float x0 = s[2 * kk + (p >> 1)][(p & 1) * 2];
        const float x1 = s[2 * kk + (p >> 1)][(p & 1) * 2 + 1];
        __nv_bfloat162 hb = __floats2bfloat162_rn(x0, x1);
        float2 hf = __bfloat1622float2(hb);
        __nv_bfloat162 lb = __floats2bfloat162_rn(x0 - hf.x, x1 - hf.y);
        shA[p] = *(uint32_t*)&hb;
        slA[p] = *(uint32_t*)&lb;
      }
      #pragma unroll
      for (int dseg = 0; dseg < 4; dseg++) {
        uint32_t va = sb + O_VHI + voff + (uint32_t)(kk * 16 * APITCH + dseg * 32);
        uint32_t vh[4], vl[4];
        LDSM4T(vh[0], vh[1], vh[2], vh[3], va);
        LDSM4T(vl[0], vl[1], vl[2], vl[3], va + AMAT);
        #pragma unroll
        for (int t2 = 0; t2 < 2; t2++) {
          const int nt = dseg * 2 + t2;
          const int q = t2 * 2;
          MMA16816(acc[nt], shA[0], shA[1], shA[2], shA[3], vh[q], vh[q + 1]);
          MMA16816(acc[nt], shA[0], shA[1], shA[2], shA[3], vl[q], vl[q + 1]);
          MMA16816(acc[nt], slA[0], slA[1], slA[2], slA[3], vh[q], vh[q + 1]);
        }
      }
    }
  }

  // ---- epilogue: rowsum reduce + cross-warp j-half sum + normalize + write planes ----
  __syncthreads();
  {
    const int r0l = wm + (lane >> 2);
    const int slot = (wid >> 2) * 4 + (lane & 3);
    rs[r0l * 8 + slot]       = rsum0;
    rs[(r0l + 8) * 8 + slot] = rsum1;
  }
  float* xch = (float*)(smc + O_KHI);   // [64][68] partial-out exchange
  if (wid >= 4) {
    const int r0l = wm + (lane >> 2), r1l = r0l + 8;
    #pragma unroll
    for (int nt = 0; nt < 8; nt++) {
      const int col = nt * 8 + (lane & 3) * 2;
      *(float2*)&xch[r0l * 68 + col] = make_float2(acc[nt][0], acc[nt][1]);
      *(float2*)&xch[r1l * 68 + col] = make_float2(acc[nt][2], acc[nt][3]);
    }
  }
  __syncthreads();
  if (wid < 4) {
    const int r0l = wm + (lane >> 2), r1l = r0l + 8;
    float t0 = 0.f, t1 = 0.f;
    #pragma unroll
    for (int g = 0; g < 8; g++) { t0 += rs[r0l * 8 + g]; t1 += rs[r1l * 8 + g]; }
    const float inv0 = 1.f / (t0 + 1e-6f);
    const float inv1 = 1.f / (t1 + 1e-6f);
    #pragma unroll
    for (int nt = 0; nt < 8; nt++) {
      const int col = nt * 8 + (lane & 3) * 2;
      float2 p0 = *(float2*)&xch[r0l * 68 + col];
      float2 p1 = *(float2*)&xch[r1l * 68 + col];
      float o00 = (acc[nt][0] + p0.x) * inv0, o01 = (acc[nt][1] + p0.y) * inv0;
      float o10 = (acc[nt][2] + p1.x) * inv1, o11 = (acc[nt][3] + p1.y) * inv1;
      const size_t a0 = ((size_t)(b * Nn + i0 + r0l)) * Cc + h * Dd + col;
      const size_t a1 = ((size_t)(b * Nn + i0 + r1l)) * Cc + h * Dd + col;
      __nv_bfloat162 hb; float2 hf; __nv_bfloat162 lb;
      hb = __floats2bfloat162_rn(o00, o01); hf = __bfloat1622float2(hb);
      lb = __floats2bfloat162_rn(o00 - hf.x, o01 - hf.y);
      *(uint32_t*)(g_aohi + a0) = *(uint32_t*)&hb;
      *(uint32_t*)(g_aolo + a0) = *(uint32_t*)&lb;
      hb = __floats2bfloat162_rn(o10, o11); hf = __bfloat1622float2(hb);
      lb = __floats2bfloat162_rn(o10 - hf.x, o11 - hf.y);
      *(uint32_t*)(g_aohi + a1) = *(uint32_t*)&hb;
      *(uint32_t*)(g_aolo + a1) = *(uint32_t*)&lb;
    }
  }
}

// ---------------- launch ----------------
extern "C" void kernel_launch(void* const* d_in, const int* in_sizes, int n_in,
                              void* d_out, int out_size)
{
  const float* x     = (const float*)d_in[0];
  const float* Wqkv  = (const float*)d_in[1];
  const float* Wa    = (const float*)d_in[2];
  const float* ba    = (const float*)d_in[3];
  const float* Wproj = (const float*)d_in[4];
  const float* bproj = (const float*)d_in[5];
  float* out = (float*)d_out;

  float *qkv, *cbuf;
  __nv_bfloat16 *hip, *lop, *xhi, *xlo, *w1hi, *w1lo, *w2hi, *w2lo, *aohi, *aolo;
  cudaGetSymbolAddress((void**)&qkv,  g_qkv);
  cudaGetSymbolAddress((void**)&cbuf, g_c);
  cudaGetSymbolAddress((void**)&hip,  g_hi);
  cudaGetSymbolAddress((void**)&lop,  g_lo);
  cudaGetSymbolAddress((void**)&xhi,  g_xhi);   cudaGetSymbolAddress((void**)&xlo,  g_xlo);
  cudaGetSymbolAddress((void**)&w1hi, g_w1hi);  cudaGetSymbolAddress((void**)&w1lo, g_w1lo);
  cudaGetSymbolAddress((void**)&w2hi, g_w2hi);  cudaGetSymbolAddress((void**)&w2lo, g_w2lo);
  cudaGetSymbolAddress((void**)&aohi, g_aohi);  cudaGetSymbolAddress((void**)&aolo, g_aolo);

  cudaFuncSetAttribute(attn_kernel, cudaFuncAttributeMaxDynamicSharedMemorySize, ASMEM);
  cudaFuncSetAttribute(gemm_mma, cudaFuncAttributeMaxDynamicSharedMemorySize, GSMEM);

  // 0) split x / Wqkv / Wproj into bf16 hi/lo planes
  const int nx = Bb * Nn * Cc, nw1 = 3 * Cc * Cc, nw2 = Cc * Cc;
  split_planes<<<(nx  / 4 + 255) / 256, 256>>>(x,     xhi,  xlo,  nx);
  split_planes<<<(nw1 / 4 + 255) / 256, 256>>>(Wqkv,  w1hi, w1lo, nw1);
  split_planes<<<(nw2 / 4 + 255) / 256, 256>>>(Wproj, w2hi, w2lo, nw2);
  // 1) qkv = x @ Wqkv^T (bf16 mma, 3-pass, cp.async 3-stage)
  gemm_mma<<<dim3(3 * Cc / 128, Bb * Nn / 128), 256, GSMEM>>>(
      xhi, xlo, w1hi, w1lo, nullptr, qkv, Bb * Nn, 3 * Cc, Cc);
  // 2) gate logits
  gate_logits<<<Bb * Nn / 8, 256>>>(x, Wa, ba);
  // 3) prefix-sum of log gates per (b,h)
  gate_scan<<<Bb * Hh, 1024>>>();
  // 4) q/k norm + split qkv into bf16 hi/lo planes
  qkv_split<<<Bb * Nn, 256>>>();
  // 5) attention (register-resident S + dead-tile skipping; writes ao planes)
  attn_kernel<<<dim3(Bb * Hh, Nn / 64), 256, ASMEM>>>(hip, lop, cbuf);
  // 6) out = ao @ Wproj^T + bproj (plane inputs)
  gemm_mma<<<dim3(Cc / 128, Bb * Nn / 128), 256, GSMEM>>>(
      aohi, aolo, w2hi, w2lo, bproj, out, Bb * Nn, Cc, Cc);
}